// round 1
// baseline (speedup 1.0000x reference)
#include <cuda_runtime.h>
#include <math.h>

#define B_   1024
#define D_   2048
#define U_   4096
#define BR_  4
#define HID_ 32
#define K_   (D_ * BR_)   // 8192

// ---------------- device scratch (static, allocation-free) ----------------
__device__ float g_gate[B_ * BR_];   // softmax gating [B,4]
__device__ float g_hid[HID_];        // MLP hidden [32]
__device__ float g_cm[U_];           // connectivity * mask [U]
__device__ float g_xt[B_ * K_];      // x~ [B, 8192]  (x[b,d]*g[b,k])
__device__ float g_wt[K_ * U_];      // W~ [8192, 4096] (w*sigmoid(delay), (d,k)-major rows)

// ---------------- K1: gating = softmax(x @ Wg + bg) over 4 branches -------
__global__ void gating_kernel(const float* __restrict__ x,
                              const float* __restrict__ Wg,
                              const float* __restrict__ bg) {
    int b = blockIdx.x, tid = threadIdx.x;
    const float* xr = x + b * D_;
    float p0 = 0.f, p1 = 0.f, p2 = 0.f, p3 = 0.f;
    for (int d = tid; d < D_; d += 256) {
        float xv = xr[d];
        float4 wv = *(const float4*)(Wg + d * 4);
        p0 += xv * wv.x; p1 += xv * wv.y; p2 += xv * wv.z; p3 += xv * wv.w;
    }
    __shared__ float s[256][4];
    s[tid][0] = p0; s[tid][1] = p1; s[tid][2] = p2; s[tid][3] = p3;
    __syncthreads();
    for (int off = 128; off > 0; off >>= 1) {
        if (tid < off) {
            #pragma unroll
            for (int k = 0; k < 4; k++) s[tid][k] += s[tid + off][k];
        }
        __syncthreads();
    }
    if (tid == 0) {
        float l[4], m = -1e30f;
        #pragma unroll
        for (int k = 0; k < 4; k++) { l[k] = s[0][k] + bg[k]; m = fmaxf(m, l[k]); }
        float e[4], sum = 0.f;
        #pragma unroll
        for (int k = 0; k < 4; k++) { e[k] = expf(l[k] - m); sum += e[k]; }
        float inv = 1.f / sum;
        #pragma unroll
        for (int k = 0; k < 4; k++) g_gate[b * 4 + k] = e[k] * inv;
    }
}

// ---------------- K2: h = relu(avg @ W1 + b1), [32] ----------------------
__global__ void hidden_kernel(const float* __restrict__ avg,
                              const float* __restrict__ W1,
                              const float* __restrict__ b1) {
    int tid = threadIdx.x;
    int j = tid & 31, grp = tid >> 5;   // 8 groups of 32 lanes
    float p = 0.f;
    for (int u = grp; u < U_; u += 8)
        p += avg[u] * W1[u * HID_ + j];
    __shared__ float s[8][32];
    s[grp][j] = p;
    __syncthreads();
    if (grp == 0) {
        float sum = 0.f;
        #pragma unroll
        for (int g = 0; g < 8; g++) sum += s[g][j];
        g_hid[j] = fmaxf(sum + b1[j], 0.f);
    }
}

// ---------------- K3: cm = sigmoid(h @ W2 + b2) * mask, [U] --------------
__global__ void conn_kernel(const float* __restrict__ W2,
                            const float* __restrict__ b2,
                            const float* __restrict__ mask) {
    __shared__ float h[HID_];
    int tid = threadIdx.x;
    if (tid < HID_) h[tid] = g_hid[tid];
    __syncthreads();
    int u = blockIdx.x * 256 + tid;
    float acc = b2[u];
    #pragma unroll
    for (int j = 0; j < HID_; j++) acc += h[j] * W2[j * U_ + u];
    g_cm[u] = mask[u] / (1.f + expf(-acc));
}

// ---------------- K4: x~[b, 4d+k] = x[b,d] * g[b,k] ----------------------
__global__ void xt_kernel(const float* __restrict__ x) {
    int idx = blockIdx.x * 256 + threadIdx.x;   // over B*D
    int b = idx >> 11;                          // / 2048
    float xv = x[idx];
    float4 gv = *(const float4*)(g_gate + b * 4);
    float4 o;
    o.x = xv * gv.x; o.y = xv * gv.y; o.z = xv * gv.z; o.w = xv * gv.w;
    *(float4*)(g_xt + (size_t)idx * 4) = o;     // row b stride 8192 = idx*4
}

// ---------------- K5: W~[4d+k, u] = w[d,u,k] * sigmoid(delay[d,u,k]) -----
__global__ void wt_kernel(const float* __restrict__ w,
                          const float* __restrict__ delay) {
    int idx = blockIdx.x * 256 + threadIdx.x;   // over D*U, u fastest
    int d = idx >> 12;                          // / 4096
    int u = idx & 4095;
    float4 wv = *(const float4*)(w + (size_t)idx * 4);
    float4 dv = *(const float4*)(delay + (size_t)idx * 4);
    float m0 = wv.x / (1.f + __expf(-dv.x));
    float m1 = wv.y / (1.f + __expf(-dv.y));
    float m2 = wv.z / (1.f + __expf(-dv.z));
    float m3 = wv.w / (1.f + __expf(-dv.w));
    int row = d * 4;
    g_wt[(size_t)(row + 0) * U_ + u] = m0;
    g_wt[(size_t)(row + 1) * U_ + u] = m1;
    g_wt[(size_t)(row + 2) * U_ + u] = m2;
    g_wt[(size_t)(row + 3) * U_ + u] = m3;
}

// ---------------- K6: GEMM [1024,8192]x[8192,4096] + fused epilogue ------
// 128x128 blocktile, BK=8, 8x8 threadtile, 256 threads.
__global__ __launch_bounds__(256, 2)
void gemm_kernel(const float* __restrict__ bias, float* __restrict__ out) {
    const int tid = threadIdx.x;
    const int bn = blockIdx.x, bm = blockIdx.y;
    const int tx = tid & 15, ty = tid >> 4;

    // --- data-driven tile skip: whole N-tile masked out -> write zeros ---
    float cmv = (tid < 128) ? g_cm[bn * 128 + tid] : 0.f;
    if (!__syncthreads_or(cmv != 0.f)) {
        int col4 = (tid & 31) * 4;
        int r0 = tid >> 5;
        float4 z = make_float4(0.f, 0.f, 0.f, 0.f);
        #pragma unroll
        for (int r = 0; r < 16; r++) {
            int row = bm * 128 + r0 + r * 8;
            *(float4*)(out + (size_t)row * U_ + bn * 128 + col4) = z;
        }
        return;
    }

    __shared__ float As[8][128];
    __shared__ float Bs[8][128];
    float acc[8][8] = {};

    const float* Aptr = g_xt + (size_t)(bm * 128) * K_;
    const float* Bptr = g_wt + bn * 128;
    const int arow = tid >> 1, acol = (tid & 1) * 4;
    const int brow = tid >> 5, bcol = (tid & 31) * 4;

    for (int k0 = 0; k0 < K_; k0 += 8) {
        float4 av = *(const float4*)(Aptr + (size_t)arow * K_ + k0 + acol);
        As[acol + 0][arow] = av.x;
        As[acol + 1][arow] = av.y;
        As[acol + 2][arow] = av.z;
        As[acol + 3][arow] = av.w;
        *(float4*)(&Bs[brow][bcol]) =
            *(const float4*)(Bptr + (size_t)(k0 + brow) * U_ + bcol);
        __syncthreads();

        #pragma unroll
        for (int kk = 0; kk < 8; kk++) {
            float a[8], bf[8];
            *(float4*)(a)      = *(float4*)(&As[kk][ty * 8]);
            *(float4*)(a + 4)  = *(float4*)(&As[kk][ty * 8 + 4]);
            *(float4*)(bf)     = *(float4*)(&Bs[kk][tx * 8]);
            *(float4*)(bf + 4) = *(float4*)(&Bs[kk][tx * 8 + 4]);
            #pragma unroll
            for (int i = 0; i < 8; i++)
                #pragma unroll
                for (int j = 0; j < 8; j++)
                    acc[i][j] += a[i] * bf[j];
        }
        __syncthreads();
    }

    // --- epilogue: + sum_k g[b,k]*bias[u,k], * cm[u], relu ---
    float  cmr[8];
    float4 bsr[8];
    #pragma unroll
    for (int j = 0; j < 8; j++) {
        int u = bn * 128 + tx * 8 + j;
        cmr[j] = g_cm[u];
        bsr[j] = *(const float4*)(bias + (size_t)u * 4);
    }
    #pragma unroll
    for (int i = 0; i < 8; i++) {
        int row = bm * 128 + ty * 8 + i;
        float4 gv = *(const float4*)(g_gate + row * 4);
        float res[8];
        #pragma unroll
        for (int j = 0; j < 8; j++) {
            float v = acc[i][j]
                    + gv.x * bsr[j].x + gv.y * bsr[j].y
                    + gv.z * bsr[j].z + gv.w * bsr[j].w;
            res[j] = fmaxf(v * cmr[j], 0.f);
        }
        float* op = out + (size_t)row * U_ + bn * 128 + tx * 8;
        *(float4*)(op)     = *(float4*)(res);
        *(float4*)(op + 4) = *(float4*)(res + 4);
    }
}

// ---------------- launch ----------------
extern "C" void kernel_launch(void* const* d_in, const int* in_sizes, int n_in,
                              void* d_out, int out_size) {
    const float* inputs = (const float*)d_in[0];
    const float* w      = (const float*)d_in[1];
    const float* bias   = (const float*)d_in[2];
    const float* delay  = (const float*)d_in[3];
    const float* Wg     = (const float*)d_in[4];
    const float* bg     = (const float*)d_in[5];
    const float* W1     = (const float*)d_in[6];
    const float* b1     = (const float*)d_in[7];
    const float* W2     = (const float*)d_in[8];
    const float* b2     = (const float*)d_in[9];
    const float* mask   = (const float*)d_in[10];
    const float* avg    = (const float*)d_in[11];
    float* out = (float*)d_out;

    gating_kernel<<<B_, 256>>>(inputs, Wg, bg);
    hidden_kernel<<<1, 256>>>(avg, W1, b1);
    conn_kernel<<<U_ / 256, 256>>>(W2, b2, mask);
    xt_kernel<<<(B_ * D_) / 256, 256>>>(inputs);
    wt_kernel<<<(D_ * U_) / 256, 256>>>(w, delay);
    gemm_kernel<<<dim3(U_ / 128, B_ / 128), 256>>>(bias, out);
}

// round 4
// speedup vs baseline: 2.8692x; 2.8692x over previous
#include <cuda_runtime.h>
#include <math.h>
#include <stdint.h>

#define B_   1024
#define D_   2048
#define U_   4096
#define BR_  4
#define HID_ 32
#define K_   (D_ * BR_)   // 8192

#define BM 128
#define BN 128
#define BK 16
#define AS_STRIDE 20
#define BS_STRIDE 136

// ---------------- device scratch (static, allocation-free) ----------------
__device__ float g_gate[B_ * BR_];   // softmax gating [B,4]
__device__ float g_hid[HID_];        // MLP hidden [32]
__device__ float g_cm[U_];           // connectivity * mask [U]
__device__ float g_xt[B_ * K_];      // x~ [B, 8192]  (x[b,d]*g[b,k], tf32-rounded)
__device__ float g_wt[K_ * U_];      // W~ [8192, 4096] (w*sigmoid(delay), tf32-rounded)

// ---------------- helpers ----------------
__device__ __forceinline__ float tf32_rna(float x) {
    float r;
    asm("cvt.rna.tf32.f32 %0, %1;" : "=f"(r) : "f"(x));
    return r;
}
__device__ __forceinline__ void cp_async16(void* smem, const void* gmem) {
    uint32_t s = (uint32_t)__cvta_generic_to_shared(smem);
    asm volatile("cp.async.cg.shared.global [%0], [%1], 16;\n" :: "r"(s), "l"(gmem));
}
__device__ __forceinline__ void mma_tf32(float& c0, float& c1, float& c2, float& c3,
                                         uint32_t a0, uint32_t a1, uint32_t a2, uint32_t a3,
                                         uint32_t b0, uint32_t b1) {
    asm volatile(
        "mma.sync.aligned.m16n8k8.row.col.f32.tf32.tf32.f32 "
        "{%0,%1,%2,%3}, {%4,%5,%6,%7}, {%8,%9}, {%0,%1,%2,%3};\n"
        : "+f"(c0), "+f"(c1), "+f"(c2), "+f"(c3)
        : "r"(a0), "r"(a1), "r"(a2), "r"(a3), "r"(b0), "r"(b1));
}

// ---------------- K1: gating = softmax(x @ Wg + bg) over 4 branches -------
__global__ void gating_kernel(const float* __restrict__ x,
                              const float* __restrict__ Wg,
                              const float* __restrict__ bg) {
    int b = blockIdx.x, tid = threadIdx.x;
    const float* xr = x + b * D_;
    float p0 = 0.f, p1 = 0.f, p2 = 0.f, p3 = 0.f;
    for (int d = tid; d < D_; d += 256) {
        float xv = xr[d];
        float4 wv = *(const float4*)(Wg + d * 4);
        p0 += xv * wv.x; p1 += xv * wv.y; p2 += xv * wv.z; p3 += xv * wv.w;
    }
    __shared__ float s[256][4];
    s[tid][0] = p0; s[tid][1] = p1; s[tid][2] = p2; s[tid][3] = p3;
    __syncthreads();
    for (int off = 128; off > 0; off >>= 1) {
        if (tid < off) {
            #pragma unroll
            for (int k = 0; k < 4; k++) s[tid][k] += s[tid + off][k];
        }
        __syncthreads();
    }
    if (tid == 0) {
        float l[4], m = -1e30f;
        #pragma unroll
        for (int k = 0; k < 4; k++) { l[k] = s[0][k] + bg[k]; m = fmaxf(m, l[k]); }
        float e[4], sum = 0.f;
        #pragma unroll
        for (int k = 0; k < 4; k++) { e[k] = expf(l[k] - m); sum += e[k]; }
        float inv = 1.f / sum;
        #pragma unroll
        for (int k = 0; k < 4; k++) g_gate[b * 4 + k] = e[k] * inv;
    }
}

// ---------------- K2: h = relu(avg @ W1 + b1), [32] ----------------------
__global__ void hidden_kernel(const float* __restrict__ avg,
                              const float* __restrict__ W1,
                              const float* __restrict__ b1) {
    int tid = threadIdx.x;
    int j = tid & 31, grp = tid >> 5;
    float p = 0.f;
    for (int u = grp; u < U_; u += 8)
        p += avg[u] * W1[u * HID_ + j];
    __shared__ float s[8][32];
    s[grp][j] = p;
    __syncthreads();
    if (grp == 0) {
        float sum = 0.f;
        #pragma unroll
        for (int g = 0; g < 8; g++) sum += s[g][j];
        g_hid[j] = fmaxf(sum + b1[j], 0.f);
    }
}

// ---------------- K3: cm = sigmoid(h @ W2 + b2) * mask, [U] --------------
__global__ void conn_kernel(const float* __restrict__ W2,
                            const float* __restrict__ b2,
                            const float* __restrict__ mask) {
    __shared__ float h[HID_];
    int tid = threadIdx.x;
    if (tid < HID_) h[tid] = g_hid[tid];
    __syncthreads();
    int u = blockIdx.x * 256 + tid;
    float acc = b2[u];
    #pragma unroll
    for (int j = 0; j < HID_; j++) acc += h[j] * W2[j * U_ + u];
    g_cm[u] = mask[u] / (1.f + expf(-acc));
}

// ---------------- K4: x~[b, 4d+k] = tf32(x[b,d] * g[b,k]) ----------------
__global__ void xt_kernel(const float* __restrict__ x) {
    int idx = blockIdx.x * 256 + threadIdx.x;   // over B*D
    int b = idx >> 11;
    float xv = x[idx];
    float4 gv = *(const float4*)(g_gate + b * 4);
    float4 o;
    o.x = tf32_rna(xv * gv.x); o.y = tf32_rna(xv * gv.y);
    o.z = tf32_rna(xv * gv.z); o.w = tf32_rna(xv * gv.w);
    *(float4*)(g_xt + (size_t)idx * 4) = o;
}

// ---------------- K5: W~[4d+k, u] = tf32(w[d,u,k] * sigmoid(delay)) ------
__global__ void wt_kernel(const float* __restrict__ w,
                          const float* __restrict__ delay) {
    int idx = blockIdx.x * 256 + threadIdx.x;   // over D*U, u fastest
    int d = idx >> 12;
    int u = idx & 4095;
    float4 wv = *(const float4*)(w + (size_t)idx * 4);
    float4 dv = *(const float4*)(delay + (size_t)idx * 4);
    float m0 = tf32_rna(wv.x / (1.f + __expf(-dv.x)));
    float m1 = tf32_rna(wv.y / (1.f + __expf(-dv.y)));
    float m2 = tf32_rna(wv.z / (1.f + __expf(-dv.z)));
    float m3 = tf32_rna(wv.w / (1.f + __expf(-dv.w)));
    int row = d * 4;
    g_wt[(size_t)(row + 0) * U_ + u] = m0;
    g_wt[(size_t)(row + 1) * U_ + u] = m1;
    g_wt[(size_t)(row + 2) * U_ + u] = m2;
    g_wt[(size_t)(row + 3) * U_ + u] = m3;
}

// ---------------- K6: tf32 tensor-core GEMM + fused epilogue -------------
// grid: (M/128, N/128)  [M fastest -> A + partial B resident in L2 per wave]
__global__ __launch_bounds__(256, 2)
void gemm_tf32_kernel(const float* __restrict__ bias, float* __restrict__ out) {
    const int tid = threadIdx.x;
    const int bm = blockIdx.x, bn = blockIdx.y;

    // --- data-driven tile skip: whole N-tile masked -> write zeros ---
    float cmv = (tid < 128) ? g_cm[bn * 128 + tid] : 0.f;
    if (!__syncthreads_or(cmv != 0.f)) {
        int col4 = (tid & 31) * 4;
        int r0 = tid >> 5;
        float4 z = make_float4(0.f, 0.f, 0.f, 0.f);
        #pragma unroll
        for (int r = 0; r < 16; r++) {
            int row = bm * 128 + r0 + r * 8;
            *(float4*)(out + (size_t)row * U_ + bn * 128 + col4) = z;
        }
        return;
    }

    __shared__ float As[2][BM][AS_STRIDE];   // [buf][m][k], stride 20
    __shared__ float Bs[2][BK][BS_STRIDE];   // [buf][k][n], stride 136

    const int wid = tid >> 5, lane = tid & 31;
    const int wm = (wid >> 2) * 64;          // warp M offset (2 warp-rows)
    const int wn = (wid & 3) * 32;           // warp N offset (4 warp-cols)
    const int g = lane >> 2, tig = lane & 3;

    float acc[4][4][4];
    #pragma unroll
    for (int i = 0; i < 4; i++)
        #pragma unroll
        for (int j = 0; j < 4; j++)
            #pragma unroll
            for (int r = 0; r < 4; r++) acc[i][j][r] = 0.f;

    const float* Ag = g_xt + (size_t)(bm * 128) * K_;
    const float* Bg = g_wt + bn * 128;

    // load indices (2 float4s each for A and B per thread)
    const int ar0 = tid >> 2,  ac0 = (tid & 3) * 4;
    const int br0 = tid >> 5,  bc0 = (tid & 31) * 4;

    // prologue: tile 0 into buf 0
    {
        #pragma unroll
        for (int i = 0; i < 2; i++)
            cp_async16(&As[0][ar0 + i * 64][ac0], Ag + (size_t)(ar0 + i * 64) * K_ + ac0);
        #pragma unroll
        for (int i = 0; i < 2; i++)
            cp_async16(&Bs[0][br0 + i * 8][bc0], Bg + (size_t)(br0 + i * 8) * U_ + bc0);
        asm volatile("cp.async.commit_group;\n");
    }

    const int NITER = K_ / BK;   // 512
    for (int t = 0; t < NITER; t++) {
        const int cur = t & 1;
        if (t + 1 < NITER) {
            const int nxt = cur ^ 1;
            const int k0 = (t + 1) * BK;
            #pragma unroll
            for (int i = 0; i < 2; i++)
                cp_async16(&As[nxt][ar0 + i * 64][ac0], Ag + (size_t)(ar0 + i * 64) * K_ + k0 + ac0);
            #pragma unroll
            for (int i = 0; i < 2; i++)
                cp_async16(&Bs[nxt][br0 + i * 8][bc0], Bg + (size_t)(k0 + br0 + i * 8) * U_ + bc0);
            asm volatile("cp.async.commit_group;\n");
            asm volatile("cp.async.wait_group 1;\n");
        } else {
            asm volatile("cp.async.wait_group 0;\n");
        }
        __syncthreads();

        #pragma unroll
        for (int ks = 0; ks < BK; ks += 8) {
            uint32_t af[4][4], bf[4][2];
            #pragma unroll
            for (int mi = 0; mi < 4; mi++) {
                int r = wm + mi * 16;
                af[mi][0] = __float_as_uint(As[cur][r + g][ks + tig]);
                af[mi][1] = __float_as_uint(As[cur][r + g + 8][ks + tig]);
                af[mi][2] = __float_as_uint(As[cur][r + g][ks + tig + 4]);
                af[mi][3] = __float_as_uint(As[cur][r + g + 8][ks + tig + 4]);
            }
            #pragma unroll
            for (int ni = 0; ni < 4; ni++) {
                int c = wn + ni * 8 + g;
                bf[ni][0] = __float_as_uint(Bs[cur][ks + tig][c]);
                bf[ni][1] = __float_as_uint(Bs[cur][ks + tig + 4][c]);
            }
            #pragma unroll
            for (int mi = 0; mi < 4; mi++)
                #pragma unroll
                for (int ni = 0; ni < 4; ni++)
                    mma_tf32(acc[mi][ni][0], acc[mi][ni][1], acc[mi][ni][2], acc[mi][ni][3],
                             af[mi][0], af[mi][1], af[mi][2], af[mi][3],
                             bf[ni][0], bf[ni][1]);
        }
        __syncthreads();
    }

    // --- epilogue: + sum_k gate[b,k]*bias[u,k], * cm[u], relu ---
    #pragma unroll
    for (int ni = 0; ni < 4; ni++) {
        int u0 = bn * 128 + wn + ni * 8 + 2 * tig;
        float cm0 = g_cm[u0], cm1 = g_cm[u0 + 1];
        float4 bs0 = *(const float4*)(bias + (size_t)u0 * 4);
        float4 bs1 = *(const float4*)(bias + (size_t)(u0 + 1) * 4);
        #pragma unroll
        for (int mi = 0; mi < 4; mi++) {
            int r0 = bm * 128 + wm + mi * 16 + g;
            int r1 = r0 + 8;
            float4 g0 = *(const float4*)(g_gate + r0 * 4);
            float4 g1 = *(const float4*)(g_gate + r1 * 4);
            float v0 = acc[mi][ni][0] + g0.x * bs0.x + g0.y * bs0.y + g0.z * bs0.z + g0.w * bs0.w;
            float v1 = acc[mi][ni][1] + g0.x * bs1.x + g0.y * bs1.y + g0.z * bs1.z + g0.w * bs1.w;
            float v2 = acc[mi][ni][2] + g1.x * bs0.x + g1.y * bs0.y + g1.z * bs0.z + g1.w * bs0.w;
            float v3 = acc[mi][ni][3] + g1.x * bs1.x + g1.y * bs1.y + g1.z * bs1.z + g1.w * bs1.w;
            float2 o0 = make_float2(fmaxf(v0 * cm0, 0.f), fmaxf(v1 * cm1, 0.f));
            float2 o1 = make_float2(fmaxf(v2 * cm0, 0.f), fmaxf(v3 * cm1, 0.f));
            *(float2*)(out + (size_t)r0 * U_ + u0) = o0;
            *(float2*)(out + (size_t)r1 * U_ + u0) = o1;
        }
    }
}

// ---------------- launch ----------------
extern "C" void kernel_launch(void* const* d_in, const int* in_sizes, int n_in,
                              void* d_out, int out_size) {
    const float* inputs = (const float*)d_in[0];
    const float* w      = (const float*)d_in[1];
    const float* bias   = (const float*)d_in[2];
    const float* delay  = (const float*)d_in[3];
    const float* Wg     = (const float*)d_in[4];
    const float* bg     = (const float*)d_in[5];
    const float* W1     = (const float*)d_in[6];
    const float* b1     = (const float*)d_in[7];
    const float* W2     = (const float*)d_in[8];
    const float* b2     = (const float*)d_in[9];
    const float* mask   = (const float*)d_in[10];
    const float* avg    = (const float*)d_in[11];
    float* out = (float*)d_out;

    gating_kernel<<<B_, 256>>>(inputs, Wg, bg);
    hidden_kernel<<<1, 256>>>(avg, W1, b1);
    conn_kernel<<<U_ / 256, 256>>>(W2, b2, mask);
    xt_kernel<<<(B_ * D_) / 256, 256>>>(inputs);
    wt_kernel<<<(D_ * U_) / 256, 256>>>(w, delay);
    gemm_tf32_kernel<<<dim3(B_ / 128, U_ / 128), 256>>>(bias, out);
}